// round 1
// baseline (speedup 1.0000x reference)
#include <cuda_runtime.h>
#include <stdint.h>

#define NANCH 9
#define NPIX  1024
#define NBOX  9216          // NPIX * NANCH
#define NWORDS 144          // ceil(NBOX/64)
#define SORT_CAP 16384
#define W1ELEMS (9*1280*256)

// ---------------- device scratch (no allocations allowed) ----------------
__device__ float g_w1t[W1ELEMS];                         // w1 repacked [tap][c][oc]
__device__ float g_h[256 * NPIX];                        // conv1 output
__device__ float g_boxes[NBOX * 4];
__device__ float g_conf[NBOX];
__device__ unsigned long long g_items[SORT_CAP];         // sort keys: (~conf_bits<<32)|idx
__device__ int g_count;
__device__ unsigned long long g_mask[(size_t)NBOX * NWORDS];
__device__ unsigned char g_keep[NBOX];

// ---------------- init ----------------
__global__ void k_init() {
    int i = blockIdx.x * 256 + threadIdx.x;
    if (i < SORT_CAP) g_items[i] = ~0ULL;   // pad keys sort to the end
    if (i < NBOX)     g_keep[i] = 0;
    if (i == 0)       g_count = 0;
}

// ---------------- repack w1 (o,c,t) -> (t,c,o) for coalesced GEMM loads ----------------
__global__ void k_repack(const float* __restrict__ w1) {
    int i = blockIdx.x * 256 + threadIdx.x;
    if (i >= W1ELEMS) return;
    int o  = i & 255;
    int c  = (i >> 8) % 1280;
    int tp = i / (1280 * 256);
    g_w1t[i] = w1[(o * 1280 + c) * 9 + tp];
}

// ---------------- conv1: 3x3 1280->256 + leaky relu, implicit GEMM ----------------
// block: 32 oc x 32 px (one image row), 128 threads, each 2oc x 4px
__global__ void __launch_bounds__(128) k_conv1(const float* __restrict__ feat,
                                               const float* __restrict__ b1) {
    __shared__ float As[32][32];   // [k][oc]
    __shared__ float Bs[32][32];   // [k][px]
    const int ocBase = blockIdx.x * 32;
    const int y   = blockIdx.y;
    const int tid = threadIdx.x;
    const int oc2 = (tid >> 3) * 2;   // 0..30 step 2
    const int px4 = (tid & 7) * 4;    // 0..28 step 4
    const int lrow = tid >> 3;        // 0..15
    const int lcol = (tid & 7) * 4;   // 0..28

    float acc[2][4];
#pragma unroll
    for (int i = 0; i < 2; i++)
#pragma unroll
        for (int q = 0; q < 4; q++) acc[i][q] = 0.f;

    for (int tp = 0; tp < 9; ++tp) {
        const int dy = tp / 3 - 1, dx = tp % 3 - 1;
        const int ysrc = y + dy;
        const bool yok = ((unsigned)ysrc) < 32u;
        const float* wp = g_w1t + (size_t)tp * (1280 * 256) + ocBase;
        for (int c0 = 0; c0 < 1280; c0 += 32) {
            float4 a0 = *(const float4*)(wp + (c0 + lrow) * 256 + lcol);
            float4 a1 = *(const float4*)(wp + (c0 + lrow + 16) * 256 + lcol);
            float bv0[4], bv1[4];
#pragma unroll
            for (int q = 0; q < 4; q++) {
                int xs = lcol + q + dx;
                bool ok = yok && (((unsigned)xs) < 32u);
                bv0[q] = ok ? feat[(c0 + lrow) * 1024 + ysrc * 32 + xs] : 0.f;
                bv1[q] = ok ? feat[(c0 + lrow + 16) * 1024 + ysrc * 32 + xs] : 0.f;
            }
            __syncthreads();
            *(float4*)&As[lrow][lcol]      = a0;
            *(float4*)&As[lrow + 16][lcol] = a1;
#pragma unroll
            for (int q = 0; q < 4; q++) { Bs[lrow][lcol + q] = bv0[q]; Bs[lrow + 16][lcol + q] = bv1[q]; }
            __syncthreads();
#pragma unroll
            for (int kk = 0; kk < 32; ++kk) {
                float a_0 = As[kk][oc2];
                float a_1 = As[kk][oc2 + 1];
                float4 b = *(const float4*)&Bs[kk][px4];
                acc[0][0] += a_0 * b.x; acc[0][1] += a_0 * b.y;
                acc[0][2] += a_0 * b.z; acc[0][3] += a_0 * b.w;
                acc[1][0] += a_1 * b.x; acc[1][1] += a_1 * b.y;
                acc[1][2] += a_1 * b.z; acc[1][3] += a_1 * b.w;
            }
        }
    }
#pragma unroll
    for (int i = 0; i < 2; i++) {
        const int oc = ocBase + oc2 + i;
        const float bias = b1[oc];
#pragma unroll
        for (int q = 0; q < 4; q++) {
            float v = acc[i][q] + bias;
            v = (v > 0.f) ? v : 0.01f * v;
            g_h[oc * 1024 + y * 32 + px4 + q] = v;
        }
    }
}

// ---------------- conv2 (1x1) + sigmoid + box decode + valid compaction ----------------
__global__ void __launch_bounds__(256) k_conv2(const float* __restrict__ w2,
                                               const float* __restrict__ b2,
                                               const float* __restrict__ anch) {
    __shared__ float sw[5][256];
    const int t = blockIdx.x * 256 + threadIdx.x;
    const int a = t >> 10;
    const int p = t & 1023;
    const int c = threadIdx.x;
    const int F[5] = {0, 2, 3, 4, 5};
#pragma unroll
    for (int f = 0; f < 5; ++f) sw[f][c] = w2[(a * 6 + F[f]) * 256 + c];
    __syncthreads();
    float s0 = 0.f, s1 = 0.f, s2 = 0.f, s3 = 0.f, s4 = 0.f;
    for (int cc = 0; cc < 256; ++cc) {
        float hv = g_h[cc * 1024 + p];
        s0 = fmaf(sw[0][cc], hv, s0);
        s1 = fmaf(sw[1][cc], hv, s1);
        s2 = fmaf(sw[2][cc], hv, s2);
        s3 = fmaf(sw[3][cc], hv, s3);
        s4 = fmaf(sw[4][cc], hv, s4);
    }
    float logit = s0 + b2[a * 6 + 0];
    float tx = s1 + b2[a * 6 + 2];
    float ty = s2 + b2[a * 6 + 3];
    float tw = s3 + b2[a * 6 + 4];
    float th = s4 + b2[a * 6 + 5];
    float aw = anch[a * 2 + 0], ah = anch[a * 2 + 1];
    float cx = (float)(p & 31) + 0.5f;
    float cy = (float)(p >> 5) + 0.5f;
    float pcx = cx + tx * aw;
    float pcy = cy + ty * ah;
    float pw = aw * expf(tw);
    float ph = ah * expf(th);
    float conf = 1.0f / (1.0f + expf(-logit));
    int r = p * 9 + a;
    g_boxes[r * 4 + 0] = pcx - pw * 0.5f;
    g_boxes[r * 4 + 1] = pcy - ph * 0.5f;
    g_boxes[r * 4 + 2] = pcx + pw * 0.5f;
    g_boxes[r * 4 + 3] = pcy + ph * 0.5f;
    g_conf[r] = conf;
    if (conf > 0.5f) {
        int j = atomicAdd(&g_count, 1);
        unsigned int sb = __float_as_uint(conf);   // conf>0 -> uint order == float order
        g_items[j] = ((unsigned long long)(~sb) << 32) | (unsigned int)r;
    }
}

// ---------------- bitonic sort (ascending) on fixed 16384 keys ----------------
__global__ void __launch_bounds__(1024) k_sort_local() {
    __shared__ unsigned long long s[2048];
    const int base = blockIdx.x * 2048;
    const int tid = threadIdx.x;
    s[tid] = g_items[base + tid];
    s[tid + 1024] = g_items[base + tid + 1024];
    __syncthreads();
    for (int k = 2; k <= 2048; k <<= 1) {
        for (int j = k >> 1; j > 0; j >>= 1) {
            int i = ((tid & ~(j - 1)) << 1) | (tid & (j - 1));
            int l = i + j;
            bool up = (((base + i) & k) == 0);
            unsigned long long x = s[i], y = s[l];
            if (up ? (x > y) : (x < y)) { s[i] = y; s[l] = x; }
            __syncthreads();
        }
    }
    g_items[base + tid] = s[tid];
    g_items[base + tid + 1024] = s[tid + 1024];
}

__global__ void __launch_bounds__(1024) k_sort_global(int k, int j) {
    int t = blockIdx.x * 1024 + threadIdx.x;   // 8192 threads
    int i = ((t & ~(j - 1)) << 1) | (t & (j - 1));
    int l = i + j;
    bool up = ((i & k) == 0);
    unsigned long long x = g_items[i], y = g_items[l];
    if (up ? (x > y) : (x < y)) { g_items[i] = y; g_items[l] = x; }
}

__global__ void __launch_bounds__(1024) k_sort_finish(int k) {
    __shared__ unsigned long long s[2048];
    const int base = blockIdx.x * 2048;
    const int tid = threadIdx.x;
    s[tid] = g_items[base + tid];
    s[tid + 1024] = g_items[base + tid + 1024];
    __syncthreads();
    for (int j = 1024; j > 0; j >>= 1) {
        int i = ((tid & ~(j - 1)) << 1) | (tid & (j - 1));
        int l = i + j;
        bool up = (((base + i) & k) == 0);
        unsigned long long x = s[i], y = s[l];
        if (up ? (x > y) : (x < y)) { s[i] = y; s[l] = x; }
        __syncthreads();
    }
    g_items[base + tid] = s[tid];
    g_items[base + tid + 1024] = s[tid + 1024];
}

// ---------------- NMS bitmask build over sorted valid boxes ----------------
__global__ void __launch_bounds__(64) k_mask() {
    const int n = g_count;
    const int rb = blockIdx.y, cb = blockIdx.x;
    if (cb < rb) return;
    if (rb * 64 >= n) return;
    __shared__ float4 sbox[64];
    const int tid = threadIdx.x;
    const int col0 = cb * 64;
    if (col0 + tid < n) {
        int r = (unsigned int)g_items[col0 + tid];
        sbox[tid] = *(const float4*)&g_boxes[r * 4];
    }
    __syncthreads();
    const int row = rb * 64 + tid;
    if (row >= n) return;
    int rr = (unsigned int)g_items[row];
    float4 bi = *(const float4*)&g_boxes[rr * 4];
    float areai = fmaxf(bi.z - bi.x, 0.f) * fmaxf(bi.w - bi.y, 0.f);
    unsigned long long bits = 0;
    int jmax = min(64, n - col0);
    for (int jj = 0; jj < jmax; ++jj) {
        int col = col0 + jj;
        if (col <= row) continue;
        float4 bj = sbox[jj];
        float iw = fmaxf(fminf(bi.z, bj.z) - fmaxf(bi.x, bj.x), 0.f);
        float ih = fmaxf(fminf(bi.w, bj.w) - fmaxf(bi.y, bj.y), 0.f);
        float inter = iw * ih;
        float areaj = fmaxf(bj.z - bj.x, 0.f) * fmaxf(bj.w - bj.y, 0.f);
        float iou = inter / (areai + areaj - inter + 1e-8f);
        if (iou > 0.7f) bits |= (1ull << jj);
    }
    g_mask[(size_t)row * NWORDS + cb] = bits;
}

// ---------------- greedy NMS reduce (single block, blocked over 64-wide words) ----------------
__global__ void __launch_bounds__(256) k_reduce() {
    __shared__ unsigned long long s_remv[NWORDS];
    __shared__ unsigned long long s_diag[64];
    __shared__ unsigned long long s_keepw;
    const int n = g_count;
    const int nb = (n + 63) >> 6;
    const int tid = threadIdx.x;
    if (tid < NWORDS) s_remv[tid] = 0;
    __syncthreads();
    for (int w = 0; w < nb; ++w) {
        if (tid < 64) {
            int row = w * 64 + tid;
            s_diag[tid] = (row < n) ? g_mask[(size_t)row * NWORDS + w] : 0ULL;
        }
        __syncthreads();
        if (tid == 0) {
            unsigned long long cur = s_remv[w];
            int rem = n - w * 64;
            if (rem < 64) cur |= (~0ULL) << rem;   // out-of-range = suppressed
            unsigned long long keepw = 0;
#pragma unroll
            for (int b = 0; b < 64; ++b) {
                if (!((cur >> b) & 1ULL)) {
                    keepw |= 1ULL << b;
                    cur |= s_diag[b];
                }
            }
            s_remv[w] = cur;
            s_keepw = keepw;
        }
        __syncthreads();
        unsigned long long kw = s_keepw;
        for (int w2 = w + 1 + tid; w2 < nb; w2 += 256) {
            unsigned long long accv = s_remv[w2];
            unsigned long long k2 = kw;
            while (k2) {
                int b = __ffsll((long long)k2) - 1;
                k2 &= k2 - 1;
                accv |= g_mask[(size_t)(w * 64 + b) * NWORDS + w2];
            }
            s_remv[w2] = accv;
        }
        __syncthreads();
        if (tid < 64) {
            if ((s_keepw >> tid) & 1ULL) {
                int r = (unsigned int)g_items[w * 64 + tid];
                g_keep[r] = 1;
            }
        }
        __syncthreads();
    }
}

// ---------------- final output: [boxes, conf] * keep ----------------
__global__ void __launch_bounds__(256) k_output(float* __restrict__ out) {
    int i = blockIdx.x * 256 + threadIdx.x;
    if (i >= NBOX) return;
    float k = g_keep[i] ? 1.0f : 0.0f;
    float4 b = *(const float4*)&g_boxes[i * 4];
    out[i * 5 + 0] = b.x * k;
    out[i * 5 + 1] = b.y * k;
    out[i * 5 + 2] = b.z * k;
    out[i * 5 + 3] = b.w * k;
    out[i * 5 + 4] = g_conf[i] * k;
}

// ---------------- launch ----------------
extern "C" void kernel_launch(void* const* d_in, const int* in_sizes, int n_in,
                              void* d_out, int out_size) {
    const float *feat = nullptr, *anch = nullptr, *w1 = nullptr,
                *b1 = nullptr, *w2 = nullptr, *b2 = nullptr;
    for (int i = 0; i < n_in; ++i) {
        switch (in_sizes[i]) {
            case 1310720: feat = (const float*)d_in[i]; break;
            case 18:      anch = (const float*)d_in[i]; break;
            case 2949120: w1   = (const float*)d_in[i]; break;
            case 256:     b1   = (const float*)d_in[i]; break;
            case 13824:   w2   = (const float*)d_in[i]; break;
            case 54:      b2   = (const float*)d_in[i]; break;
            default: break;
        }
    }
    float* out = (float*)d_out;

    k_init<<<64, 256>>>();
    k_repack<<<W1ELEMS / 256, 256>>>(w1);
    k_conv1<<<dim3(8, 32), 128>>>(feat, b1);
    k_conv2<<<36, 256>>>(w2, b2, anch);

    // sort 16384 keys ascending
    k_sort_local<<<8, 1024>>>();
    k_sort_global<<<8, 1024>>>(4096, 2048);
    k_sort_finish<<<8, 1024>>>(4096);
    k_sort_global<<<8, 1024>>>(8192, 4096);
    k_sort_global<<<8, 1024>>>(8192, 2048);
    k_sort_finish<<<8, 1024>>>(8192);
    k_sort_global<<<8, 1024>>>(16384, 8192);
    k_sort_global<<<8, 1024>>>(16384, 4096);
    k_sort_global<<<8, 1024>>>(16384, 2048);
    k_sort_finish<<<8, 1024>>>(16384);

    k_mask<<<dim3(NWORDS, NWORDS), 64>>>();
    k_reduce<<<1, 256>>>();
    k_output<<<36, 256>>>(out);
}

// round 2
// speedup vs baseline: 2.2240x; 2.2240x over previous
#include <cuda_runtime.h>
#include <stdint.h>

#define NANCH 9
#define NPIX  1024
#define NBOX  9216          // NPIX * NANCH
#define NWORDS 144          // ceil(NBOX/64)
#define SORT_CAP 16384
#define W1ELEMS (9*1280*256)

// packed f32x2 FMA (full-rate fp32 path on sm_103a)
#define FMA2(acc, a, b) asm("fma.rn.f32x2 %0, %1, %2, %0;" : "+l"(acc) : "l"(a), "l"(b))

__device__ __forceinline__ float u64lo(unsigned long long v) {
    return __uint_as_float((unsigned)(v & 0xffffffffull));
}
__device__ __forceinline__ float u64hi(unsigned long long v) {
    return __uint_as_float((unsigned)(v >> 32));
}

// ---------------- device scratch ----------------
__device__ float g_w1t[W1ELEMS];                 // w1 repacked [tap][c][oc]
__device__ float g_hp[3][256 * NPIX];            // conv1 partial sums per ky
__device__ float g_h[256 * NPIX];                // activated hidden
__device__ float g_boxes[NBOX * 4];
__device__ float g_conf[NBOX];
__device__ unsigned long long g_items[SORT_CAP]; // (~conf_bits<<32)|idx
__device__ int g_count;
__device__ unsigned long long g_mask[(size_t)NBOX * NWORDS];
__device__ unsigned char g_keep[NBOX];

// ---------------- init ----------------
__global__ void k_init() {
    int i = blockIdx.x * 256 + threadIdx.x;
    if (i < SORT_CAP) g_items[i] = ~0ULL;
    if (i < NBOX)     g_keep[i] = 0;
    if (i == 0)       g_count = 0;
}

__global__ void k_dummy() {}

// ---------------- repack w1 (o,c,t) -> (t,c,o) ----------------
__global__ void k_repack(const float* __restrict__ w1) {
    int i = blockIdx.x * 256 + threadIdx.x;
    if (i >= W1ELEMS) return;
    int o  = i & 255;
    int c  = (i >> 8) % 1280;
    int tp = i / (1280 * 256);
    g_w1t[i] = w1[(o * 1280 + c) * 9 + tp];
}

// ---------------- conv1 split-K over ky, double-buffered, f32x2 ----------------
// grid (8, 32, 3): 32 oc x 32 px (one y row) per block, z = ky index
// 128 threads, each 2 oc x 4 px
__global__ void __launch_bounds__(128) k_conv1(const float* __restrict__ feat) {
    __shared__ float2 As[32][32];   // [k][oc], value duplicated in .x/.y
    __shared__ float  Bs[32][32];   // [k][px]

    const int ocBase = blockIdx.x * 32;
    const int y      = blockIdx.y;
    const int z      = blockIdx.z;         // ky index 0..2
    const int ysrc   = y + (z - 1);
    const bool yok   = ((unsigned)ysrc) < 32u;
    const int tid  = threadIdx.x;
    const int oc2  = (tid >> 3) * 2;
    const int px4  = (tid & 7) * 4;
    const int lrow = tid >> 3;        // 0..15
    const int lcol = (tid & 7) * 4;

    unsigned long long acc00 = 0ull, acc01 = 0ull, acc10 = 0ull, acc11 = 0ull;

    const int featRow = ysrc * 32;

    for (int dxi = 0; dxi < 3; ++dxi) {
        const int dx = dxi - 1;
        const int tp = z * 3 + dxi;
        const float* wp = g_w1t + (size_t)tp * (1280 * 256) + ocBase;

        // prologue prefetch (c0 = 0)
        float4 a0 = *(const float4*)(wp + lrow * 256 + lcol);
        float4 a1 = *(const float4*)(wp + (lrow + 16) * 256 + lcol);
        float bv0[4], bv1[4];
#pragma unroll
        for (int q = 0; q < 4; q++) {
            int xs = lcol + q + dx;
            bool ok = yok && (((unsigned)xs) < 32u);
            bv0[q] = ok ? feat[lrow * 1024 + featRow + xs] : 0.f;
            bv1[q] = ok ? feat[(lrow + 16) * 1024 + featRow + xs] : 0.f;
        }

        for (int c0 = 0; c0 < 1280; c0 += 32) {
            __syncthreads();
            // commit current regs to smem
            float4 d0 = make_float4(a0.x, a0.x, a0.y, a0.y);
            float4 d1 = make_float4(a0.z, a0.z, a0.w, a0.w);
            *(float4*)&As[lrow][lcol]     = d0;
            *(float4*)&As[lrow][lcol + 2] = d1;
            float4 e0 = make_float4(a1.x, a1.x, a1.y, a1.y);
            float4 e1 = make_float4(a1.z, a1.z, a1.w, a1.w);
            *(float4*)&As[lrow + 16][lcol]     = e0;
            *(float4*)&As[lrow + 16][lcol + 2] = e1;
#pragma unroll
            for (int q = 0; q < 4; q++) { Bs[lrow][lcol + q] = bv0[q]; Bs[lrow + 16][lcol + q] = bv1[q]; }
            __syncthreads();

            // prefetch next tile
            if (c0 + 32 < 1280) {
                const int cn = c0 + 32;
                a0 = *(const float4*)(wp + (cn + lrow) * 256 + lcol);
                a1 = *(const float4*)(wp + (cn + lrow + 16) * 256 + lcol);
#pragma unroll
                for (int q = 0; q < 4; q++) {
                    int xs = lcol + q + dx;
                    bool ok = yok && (((unsigned)xs) < 32u);
                    bv0[q] = ok ? feat[(cn + lrow) * 1024 + featRow + xs] : 0.f;
                    bv1[q] = ok ? feat[(cn + lrow + 16) * 1024 + featRow + xs] : 0.f;
                }
            }

            // compute on smem tile
#pragma unroll
            for (int kk = 0; kk < 32; ++kk) {
                unsigned long long ap0 = *(const unsigned long long*)&As[kk][oc2];
                unsigned long long ap1 = *(const unsigned long long*)&As[kk][oc2 + 1];
                ulonglong2 bp = *(const ulonglong2*)&Bs[kk][px4];
                FMA2(acc00, ap0, bp.x);
                FMA2(acc01, ap0, bp.y);
                FMA2(acc10, ap1, bp.x);
                FMA2(acc11, ap1, bp.y);
            }
        }
    }

    float* dst = g_hp[z] + (ocBase + oc2) * 1024 + y * 32 + px4;
    dst[0] = u64lo(acc00); dst[1] = u64hi(acc00);
    dst[2] = u64lo(acc01); dst[3] = u64hi(acc01);
    dst += 1024;
    dst[0] = u64lo(acc10); dst[1] = u64hi(acc10);
    dst[2] = u64lo(acc11); dst[3] = u64hi(acc11);
}

// ---------------- combine partials + bias + leaky relu ----------------
__global__ void __launch_bounds__(256) k_act(const float* __restrict__ b1) {
    int i = blockIdx.x * 256 + threadIdx.x;   // 262144 total
    float v = (g_hp[0][i] + g_hp[1][i]) + g_hp[2][i] + b1[i >> 10];
    v = (v > 0.f) ? v : 0.01f * v;
    g_h[i] = v;
}

// ---------------- conv2 (1x1) + sigmoid + decode + compaction ----------------
__global__ void __launch_bounds__(128) k_conv2(const float* __restrict__ w2,
                                               const float* __restrict__ b2,
                                               const float* __restrict__ anch) {
    __shared__ float sw[5][256];
    const int t = blockIdx.x * 128 + threadIdx.x;
    const int a = t >> 10;            // constant within a block (128 | 1024)
    const int p = t & 1023;
    const int F[5] = {0, 2, 3, 4, 5};
#pragma unroll
    for (int f = 0; f < 5; ++f)
        for (int c = threadIdx.x; c < 256; c += 128)
            sw[f][c] = w2[(a * 6 + F[f]) * 256 + c];
    __syncthreads();
    float s0 = 0.f, s1 = 0.f, s2 = 0.f, s3 = 0.f, s4 = 0.f;
#pragma unroll 4
    for (int cc = 0; cc < 256; ++cc) {
        float hv = g_h[cc * 1024 + p];
        s0 = fmaf(sw[0][cc], hv, s0);
        s1 = fmaf(sw[1][cc], hv, s1);
        s2 = fmaf(sw[2][cc], hv, s2);
        s3 = fmaf(sw[3][cc], hv, s3);
        s4 = fmaf(sw[4][cc], hv, s4);
    }
    float logit = s0 + b2[a * 6 + 0];
    float tx = s1 + b2[a * 6 + 2];
    float ty = s2 + b2[a * 6 + 3];
    float tw = s3 + b2[a * 6 + 4];
    float th = s4 + b2[a * 6 + 5];
    float aw = anch[a * 2 + 0], ah = anch[a * 2 + 1];
    float cx = (float)(p & 31) + 0.5f;
    float cy = (float)(p >> 5) + 0.5f;
    float pcx = cx + tx * aw;
    float pcy = cy + ty * ah;
    float pw = aw * expf(tw);
    float ph = ah * expf(th);
    float conf = 1.0f / (1.0f + expf(-logit));
    int r = p * 9 + a;
    g_boxes[r * 4 + 0] = pcx - pw * 0.5f;
    g_boxes[r * 4 + 1] = pcy - ph * 0.5f;
    g_boxes[r * 4 + 2] = pcx + pw * 0.5f;
    g_boxes[r * 4 + 3] = pcy + ph * 0.5f;
    g_conf[r] = conf;
    if (conf > 0.5f) {
        int j = atomicAdd(&g_count, 1);
        unsigned int sb = __float_as_uint(conf);
        g_items[j] = ((unsigned long long)(~sb) << 32) | (unsigned int)r;
    }
}

// ---------------- bitonic sort (ascending) on fixed 16384 keys ----------------
__global__ void __launch_bounds__(1024) k_sort_local() {
    __shared__ unsigned long long s[2048];
    const int base = blockIdx.x * 2048;
    const int tid = threadIdx.x;
    s[tid] = g_items[base + tid];
    s[tid + 1024] = g_items[base + tid + 1024];
    __syncthreads();
    for (int k = 2; k <= 2048; k <<= 1) {
        for (int j = k >> 1; j > 0; j >>= 1) {
            int i = ((tid & ~(j - 1)) << 1) | (tid & (j - 1));
            int l = i + j;
            bool up = (((base + i) & k) == 0);
            unsigned long long x = s[i], y = s[l];
            if (up ? (x > y) : (x < y)) { s[i] = y; s[l] = x; }
            __syncthreads();
        }
    }
    g_items[base + tid] = s[tid];
    g_items[base + tid + 1024] = s[tid + 1024];
}

__global__ void __launch_bounds__(1024) k_sort_global(int k, int j) {
    int t = blockIdx.x * 1024 + threadIdx.x;
    int i = ((t & ~(j - 1)) << 1) | (t & (j - 1));
    int l = i + j;
    bool up = ((i & k) == 0);
    unsigned long long x = g_items[i], y = g_items[l];
    if (up ? (x > y) : (x < y)) { g_items[i] = y; g_items[l] = x; }
}

__global__ void __launch_bounds__(1024) k_sort_finish(int k) {
    __shared__ unsigned long long s[2048];
    const int base = blockIdx.x * 2048;
    const int tid = threadIdx.x;
    s[tid] = g_items[base + tid];
    s[tid + 1024] = g_items[base + tid + 1024];
    __syncthreads();
    for (int j = 1024; j > 0; j >>= 1) {
        int i = ((tid & ~(j - 1)) << 1) | (tid & (j - 1));
        int l = i + j;
        bool up = (((base + i) & k) == 0);
        unsigned long long x = s[i], y = s[l];
        if (up ? (x > y) : (x < y)) { s[i] = y; s[l] = x; }
        __syncthreads();
    }
    g_items[base + tid] = s[tid];
    g_items[base + tid + 1024] = s[tid + 1024];
}

// ---------------- NMS bitmask build ----------------
__global__ void __launch_bounds__(64) k_mask() {
    const int n = g_count;
    const int rb = blockIdx.y, cb = blockIdx.x;
    if (cb < rb) return;
    if (rb * 64 >= n) return;
    if (cb * 64 >= n) return;
    __shared__ float4 sbox[64];
    const int tid = threadIdx.x;
    const int col0 = cb * 64;
    if (col0 + tid < n) {
        int r = (unsigned int)g_items[col0 + tid];
        sbox[tid] = *(const float4*)&g_boxes[r * 4];
    }
    __syncthreads();
    const int row = rb * 64 + tid;
    if (row >= n) return;
    int rr = (unsigned int)g_items[row];
    float4 bi = *(const float4*)&g_boxes[rr * 4];
    float areai = fmaxf(bi.z - bi.x, 0.f) * fmaxf(bi.w - bi.y, 0.f);
    unsigned long long bits = 0;
    int jmax = min(64, n - col0);
    for (int jj = 0; jj < jmax; ++jj) {
        int col = col0 + jj;
        if (col <= row) continue;
        float4 bj = sbox[jj];
        float iw = fmaxf(fminf(bi.z, bj.z) - fmaxf(bi.x, bj.x), 0.f);
        float ih = fmaxf(fminf(bi.w, bj.w) - fmaxf(bi.y, bj.y), 0.f);
        float inter = iw * ih;
        float areaj = fmaxf(bj.z - bj.x, 0.f) * fmaxf(bj.w - bj.y, 0.f);
        float iou = inter / (areai + areaj - inter + 1e-8f);
        if (iou > 0.7f) bits |= (1ull << jj);
    }
    g_mask[(size_t)row * NWORDS + cb] = bits;
}

// ---------------- greedy NMS reduce ----------------
__global__ void __launch_bounds__(256) k_reduce() {
    __shared__ unsigned long long s_remv[NWORDS];
    __shared__ unsigned long long s_diag[64];
    __shared__ unsigned long long s_keepw;
    const int n = g_count;
    const int nb = (n + 63) >> 6;
    const int tid = threadIdx.x;
    for (int i = tid; i < NWORDS; i += 256) s_remv[i] = 0;
    __syncthreads();
    const int q   = tid & 3;       // quarter of bits
    const int off = tid >> 2;      // word offset lane
    for (int w = 0; w < nb; ++w) {
        if (tid < 64) {
            int row = w * 64 + tid;
            s_diag[tid] = (row < n) ? g_mask[(size_t)row * NWORDS + w] : 0ULL;
        }
        __syncthreads();
        if (tid == 0) {
            unsigned long long cur = s_remv[w];
            int rem = n - w * 64;
            if (rem < 64) cur |= (~0ULL) << rem;
            unsigned long long keepw = 0;
#pragma unroll
            for (int b = 0; b < 64; ++b) {
                if (!((cur >> b) & 1ULL)) {
                    keepw |= 1ULL << b;
                    cur |= s_diag[b];
                }
            }
            s_remv[w] = cur;
            s_keepw = keepw;
        }
        __syncthreads();
        const unsigned long long kw = s_keepw;
        for (int w2 = w + 1 + off; w2 < nb; w2 += 64) {
            unsigned long long accv = 0;
#pragma unroll
            for (int bb = 0; bb < 16; ++bb) {
                int b = q * 16 + bb;
                if ((kw >> b) & 1ULL)
                    accv |= g_mask[(size_t)(w * 64 + b) * NWORDS + w2];
            }
            if (accv) atomicOr(&s_remv[w2], accv);
        }
        __syncthreads();
        if (tid < 64) {
            if ((kw >> tid) & 1ULL) {
                int r = (unsigned int)g_items[w * 64 + tid];
                g_keep[r] = 1;
            }
        }
        __syncthreads();
    }
}

// ---------------- final output ----------------
__global__ void __launch_bounds__(256) k_output(float* __restrict__ out) {
    int i = blockIdx.x * 256 + threadIdx.x;
    if (i >= NBOX) return;
    float k = g_keep[i] ? 1.0f : 0.0f;
    float4 b = *(const float4*)&g_boxes[i * 4];
    out[i * 5 + 0] = b.x * k;
    out[i * 5 + 1] = b.y * k;
    out[i * 5 + 2] = b.z * k;
    out[i * 5 + 3] = b.w * k;
    out[i * 5 + 4] = g_conf[i] * k;
}

// ---------------- launch ----------------
extern "C" void kernel_launch(void* const* d_in, const int* in_sizes, int n_in,
                              void* d_out, int out_size) {
    const float *feat = nullptr, *anch = nullptr, *w1 = nullptr,
                *b1 = nullptr, *w2 = nullptr, *b2 = nullptr;
    for (int i = 0; i < n_in; ++i) {
        switch (in_sizes[i]) {
            case 1310720: feat = (const float*)d_in[i]; break;
            case 18:      anch = (const float*)d_in[i]; break;
            case 2949120: w1   = (const float*)d_in[i]; break;
            case 256:     b1   = (const float*)d_in[i]; break;
            case 13824:   w2   = (const float*)d_in[i]; break;
            case 54:      b2   = (const float*)d_in[i]; break;
            default: break;
        }
    }
    float* out = (float*)d_out;

    k_init<<<64, 256>>>();                        // 0
    k_repack<<<W1ELEMS / 256, 256>>>(w1);         // 1
    k_dummy<<<1, 32>>>();                         // 2 (aligns conv1 with ncu capture slot)
    k_conv1<<<dim3(8, 32, 3), 128>>>(feat);       // 3
    k_act<<<1024, 256>>>(b1);                     // 4
    k_conv2<<<72, 128>>>(w2, b2, anch);           // 5

    k_sort_local<<<8, 1024>>>();
    k_sort_global<<<8, 1024>>>(4096, 2048);
    k_sort_finish<<<8, 1024>>>(4096);
    k_sort_global<<<8, 1024>>>(8192, 4096);
    k_sort_global<<<8, 1024>>>(8192, 2048);
    k_sort_finish<<<8, 1024>>>(8192);
    k_sort_global<<<8, 1024>>>(16384, 8192);
    k_sort_global<<<8, 1024>>>(16384, 4096);
    k_sort_global<<<8, 1024>>>(16384, 2048);
    k_sort_finish<<<8, 1024>>>(16384);

    k_mask<<<dim3(NWORDS, NWORDS), 64>>>();
    k_reduce<<<1, 256>>>();
    k_output<<<36, 256>>>(out);
}

// round 3
// speedup vs baseline: 2.4983x; 1.1233x over previous
#include <cuda_runtime.h>
#include <stdint.h>

#define NANCH 9
#define NPIX  1024
#define NBOX  9216          // NPIX * NANCH
#define NWORDS 144          // ceil(NBOX/64)
#define SORT_CAP 16384
#define W1ELEMS (9*1280*256)

// packed f32x2 FMA (full-rate fp32 path on sm_103a)
#define FMA2(acc, a, b) asm("fma.rn.f32x2 %0, %1, %2, %0;" : "+l"(acc) : "l"(a), "l"(b))

__device__ __forceinline__ unsigned long long dup2(float a) {
    unsigned long long r;
    asm("mov.b64 %0, {%1, %1};" : "=l"(r) : "r"(__float_as_uint(a)));
    return r;
}

// ---------------- device scratch ----------------
__device__ float g_w1t[W1ELEMS];                 // w1 repacked [tap][c][oc]
__device__ float g_hp[9][256 * NPIX];            // conv1 partial sums per tap
__device__ float g_h[256 * NPIX];                // activated hidden
__device__ float g_boxes[NBOX * 4];
__device__ float g_conf[NBOX];
__device__ unsigned long long g_items[SORT_CAP]; // (~conf_bits<<32)|idx
__device__ int g_count;
__device__ unsigned long long g_mask[(size_t)NBOX * NWORDS];
__device__ unsigned char g_keep[NBOX];

// ---------------- init ----------------
__global__ void k_init() {
    int i = blockIdx.x * 256 + threadIdx.x;
    if (i < SORT_CAP) g_items[i] = ~0ULL;
    if (i < NBOX)     g_keep[i] = 0;
    if (i == 0)       g_count = 0;
}

__global__ void k_dummy() {}

// ---------------- repack w1 (o,c,t) -> (t,c,o) ----------------
__global__ void k_repack(const float* __restrict__ w1) {
    int i = blockIdx.x * 256 + threadIdx.x;
    if (i >= W1ELEMS) return;
    int o  = i & 255;
    int c  = (i >> 8) % 1280;
    int tp = i / (1280 * 256);
    g_w1t[i] = w1[(o * 1280 + c) * 9 + tp];
}

// ---------------- conv1: split-K over 9 taps, 64oc x 64px tile, f32x2 ----------------
// grid (4, 16, 9): 64 oc x 64 px (2 y rows), z = tap. 128 threads, 4 oc x 8 px each.
__global__ void __launch_bounds__(128) k_conv1(const float* __restrict__ feat) {
    __shared__ float As[32][64];   // [k][oc]
    __shared__ float Bs[32][64];   // [k][px]

    const int ocBase = blockIdx.x * 64;
    const int y0     = blockIdx.y * 2;
    const int tp     = blockIdx.z;          // tap 0..8
    const int dy = tp / 3 - 1, dx = tp % 3 - 1;

    const int tid = threadIdx.x;
    const int og  = tid >> 3;        // 0..15 -> 4 oc
    const int pg  = tid & 7;         // 0..7  -> 8 px

    // loader mapping: 32 rows x 4 segs of 16
    const int lk = tid >> 2;         // 0..31 (k row)
    const int ls = (tid & 3) * 16;   // 0,16,32,48 (col segment)

    // B source geometry (fixed per thread): segment lies in one y row
    const int r     = ls >> 5;               // 0 or 1
    const int ysrc  = y0 + r + dy;
    const bool yok  = ((unsigned)ysrc) < 32u;
    const int xbase = (ls & 31) + dx;
    const int frow  = ysrc * 32;

    const float* wp = g_w1t + (size_t)tp * (1280 * 256) + ocBase;

    unsigned long long acc[4][4];
#pragma unroll
    for (int i = 0; i < 4; i++)
#pragma unroll
        for (int j = 0; j < 4; j++) acc[i][j] = 0ull;

    // prologue prefetch (c0 = 0)
    float4 aw0 = *(const float4*)(wp + lk * 256 + ls);
    float4 aw1 = *(const float4*)(wp + lk * 256 + ls + 4);
    float4 aw2 = *(const float4*)(wp + lk * 256 + ls + 8);
    float4 aw3 = *(const float4*)(wp + lk * 256 + ls + 12);
    float bv[16];
#pragma unroll
    for (int q = 0; q < 16; q++) {
        int xs = xbase + q;
        bool ok = yok && (((unsigned)xs) < 32u);
        bv[q] = ok ? feat[lk * 1024 + frow + xs] : 0.f;
    }

    for (int c0 = 0; c0 < 1280; c0 += 32) {
        __syncthreads();
        *(float4*)&As[lk][ls]      = aw0;
        *(float4*)&As[lk][ls + 4]  = aw1;
        *(float4*)&As[lk][ls + 8]  = aw2;
        *(float4*)&As[lk][ls + 12] = aw3;
        *(float4*)&Bs[lk][ls]      = make_float4(bv[0], bv[1], bv[2], bv[3]);
        *(float4*)&Bs[lk][ls + 4]  = make_float4(bv[4], bv[5], bv[6], bv[7]);
        *(float4*)&Bs[lk][ls + 8]  = make_float4(bv[8], bv[9], bv[10], bv[11]);
        *(float4*)&Bs[lk][ls + 12] = make_float4(bv[12], bv[13], bv[14], bv[15]);
        __syncthreads();

        // prefetch next chunk
        if (c0 + 32 < 1280) {
            const int cn = c0 + 32;
            aw0 = *(const float4*)(wp + (cn + lk) * 256 + ls);
            aw1 = *(const float4*)(wp + (cn + lk) * 256 + ls + 4);
            aw2 = *(const float4*)(wp + (cn + lk) * 256 + ls + 8);
            aw3 = *(const float4*)(wp + (cn + lk) * 256 + ls + 12);
#pragma unroll
            for (int q = 0; q < 16; q++) {
                int xs = xbase + q;
                bool ok = yok && (((unsigned)xs) < 32u);
                bv[q] = ok ? feat[(cn + lk) * 1024 + frow + xs] : 0.f;
            }
        }

        // compute
#pragma unroll
        for (int kk = 0; kk < 32; ++kk) {
            float4 a = *(const float4*)&As[kk][og * 4];
            ulonglong2 b0 = *(const ulonglong2*)&Bs[kk][pg * 8];
            ulonglong2 b1 = *(const ulonglong2*)&Bs[kk][pg * 8 + 4];
            unsigned long long d0 = dup2(a.x);
            unsigned long long d1 = dup2(a.y);
            unsigned long long d2 = dup2(a.z);
            unsigned long long d3 = dup2(a.w);
            FMA2(acc[0][0], d0, b0.x); FMA2(acc[0][1], d0, b0.y);
            FMA2(acc[0][2], d0, b1.x); FMA2(acc[0][3], d0, b1.y);
            FMA2(acc[1][0], d1, b0.x); FMA2(acc[1][1], d1, b0.y);
            FMA2(acc[1][2], d1, b1.x); FMA2(acc[1][3], d1, b1.y);
            FMA2(acc[2][0], d2, b0.x); FMA2(acc[2][1], d2, b0.y);
            FMA2(acc[2][2], d2, b1.x); FMA2(acc[2][3], d2, b1.y);
            FMA2(acc[3][0], d3, b0.x); FMA2(acc[3][1], d3, b0.y);
            FMA2(acc[3][2], d3, b1.x); FMA2(acc[3][3], d3, b1.y);
        }
    }

    // epilogue: store partials. thread's 8 px are contiguous in one y row.
    const int yout = y0 + (pg >> 2);
    const int xout = (pg * 8) & 31;
    float* dst = g_hp[tp] + (size_t)(ocBase + og * 4) * 1024 + yout * 32 + xout;
#pragma unroll
    for (int i = 0; i < 4; i++) {
#pragma unroll
        for (int j = 0; j < 4; j++)
            *(unsigned long long*)(dst + 2 * j) = acc[i][j];
        dst += 1024;
    }
}

// ---------------- combine 9 partials + bias + leaky relu ----------------
__global__ void __launch_bounds__(256) k_act(const float* __restrict__ b1) {
    int i = blockIdx.x * 256 + threadIdx.x;   // 262144 total
    float v = g_hp[0][i];
#pragma unroll
    for (int z = 1; z < 9; z++) v += g_hp[z][i];
    v += b1[i >> 10];
    v = (v > 0.f) ? v : 0.01f * v;
    g_h[i] = v;
}

// ---------------- conv2 (1x1) + sigmoid + decode + compaction ----------------
__global__ void __launch_bounds__(64) k_conv2(const float* __restrict__ w2,
                                              const float* __restrict__ b2,
                                              const float* __restrict__ anch) {
    __shared__ float sw[5][256];
    const int t = blockIdx.x * 64 + threadIdx.x;
    const int a = t >> 10;            // constant within a block (64 | 1024)
    const int p = t & 1023;
    const int F[5] = {0, 2, 3, 4, 5};
#pragma unroll
    for (int f = 0; f < 5; ++f)
        for (int c = threadIdx.x; c < 256; c += 64)
            sw[f][c] = w2[(a * 6 + F[f]) * 256 + c];
    __syncthreads();
    float s0 = 0.f, s1 = 0.f, s2 = 0.f, s3 = 0.f, s4 = 0.f;
#pragma unroll 4
    for (int cc = 0; cc < 256; ++cc) {
        float hv = g_h[cc * 1024 + p];
        s0 = fmaf(sw[0][cc], hv, s0);
        s1 = fmaf(sw[1][cc], hv, s1);
        s2 = fmaf(sw[2][cc], hv, s2);
        s3 = fmaf(sw[3][cc], hv, s3);
        s4 = fmaf(sw[4][cc], hv, s4);
    }
    float logit = s0 + b2[a * 6 + 0];
    float tx = s1 + b2[a * 6 + 2];
    float ty = s2 + b2[a * 6 + 3];
    float tw = s3 + b2[a * 6 + 4];
    float th = s4 + b2[a * 6 + 5];
    float aw = anch[a * 2 + 0], ah = anch[a * 2 + 1];
    float cx = (float)(p & 31) + 0.5f;
    float cy = (float)(p >> 5) + 0.5f;
    float pcx = cx + tx * aw;
    float pcy = cy + ty * ah;
    float pw = aw * expf(tw);
    float ph = ah * expf(th);
    float conf = 1.0f / (1.0f + expf(-logit));
    int r = p * 9 + a;
    g_boxes[r * 4 + 0] = pcx - pw * 0.5f;
    g_boxes[r * 4 + 1] = pcy - ph * 0.5f;
    g_boxes[r * 4 + 2] = pcx + pw * 0.5f;
    g_boxes[r * 4 + 3] = pcy + ph * 0.5f;
    g_conf[r] = conf;
    if (conf > 0.5f) {
        int j = atomicAdd(&g_count, 1);
        unsigned int sb = __float_as_uint(conf);
        g_items[j] = ((unsigned long long)(~sb) << 32) | (unsigned int)r;
    }
}

// ---------------- bitonic sort (ascending), 4096-elem shared chunks ----------------
__global__ void __launch_bounds__(1024) k_sort_local4k() {
    __shared__ unsigned long long s[4096];
    const int base = blockIdx.x * 4096;
    const int tid = threadIdx.x;
#pragma unroll
    for (int e = 0; e < 4; e++) s[tid + e * 1024] = g_items[base + tid + e * 1024];
    __syncthreads();
    for (int k = 2; k <= 4096; k <<= 1) {
        for (int j = k >> 1; j > 0; j >>= 1) {
#pragma unroll
            for (int e = 0; e < 2; e++) {
                int t = tid + e * 1024;                 // pair index 0..2047
                int i = ((t & ~(j - 1)) << 1) | (t & (j - 1));
                int l = i + j;
                bool up = (((base + i) & k) == 0);
                unsigned long long x = s[i], y = s[l];
                if (up ? (x > y) : (x < y)) { s[i] = y; s[l] = x; }
            }
            __syncthreads();
        }
    }
#pragma unroll
    for (int e = 0; e < 4; e++) g_items[base + tid + e * 1024] = s[tid + e * 1024];
}

__global__ void __launch_bounds__(1024) k_sort_global(int k, int j) {
    int t = blockIdx.x * 1024 + threadIdx.x;   // 8192 pair threads
    int i = ((t & ~(j - 1)) << 1) | (t & (j - 1));
    int l = i + j;
    bool up = ((i & k) == 0);
    unsigned long long x = g_items[i], y = g_items[l];
    if (up ? (x > y) : (x < y)) { g_items[i] = y; g_items[l] = x; }
}

// finish steps j<=2048 inside 4096-elem chunks, direction from global k
__global__ void __launch_bounds__(1024) k_sort_finish4k(int k) {
    __shared__ unsigned long long s[4096];
    const int base = blockIdx.x * 4096;
    const int tid = threadIdx.x;
#pragma unroll
    for (int e = 0; e < 4; e++) s[tid + e * 1024] = g_items[base + tid + e * 1024];
    __syncthreads();
    for (int j = 2048; j > 0; j >>= 1) {
#pragma unroll
        for (int e = 0; e < 2; e++) {
            int t = tid + e * 1024;
            int i = ((t & ~(j - 1)) << 1) | (t & (j - 1));
            int l = i + j;
            bool up = (((base + i) & k) == 0);
            unsigned long long x = s[i], y = s[l];
            if (up ? (x > y) : (x < y)) { s[i] = y; s[l] = x; }
        }
        __syncthreads();
    }
#pragma unroll
    for (int e = 0; e < 4; e++) g_items[base + tid + e * 1024] = s[tid + e * 1024];
}

// ---------------- NMS bitmask build ----------------
__global__ void __launch_bounds__(64) k_mask() {
    const int n = g_count;
    const int rb = blockIdx.y, cb = blockIdx.x;
    if (cb < rb) return;
    if (rb * 64 >= n) return;
    if (cb * 64 >= n) return;
    __shared__ float4 sbox[64];
    const int tid = threadIdx.x;
    const int col0 = cb * 64;
    if (col0 + tid < n) {
        int r = (unsigned int)g_items[col0 + tid];
        sbox[tid] = *(const float4*)&g_boxes[r * 4];
    }
    __syncthreads();
    const int row = rb * 64 + tid;
    if (row >= n) return;
    int rr = (unsigned int)g_items[row];
    float4 bi = *(const float4*)&g_boxes[rr * 4];
    float areai = fmaxf(bi.z - bi.x, 0.f) * fmaxf(bi.w - bi.y, 0.f);
    unsigned long long bits = 0;
    int jmax = min(64, n - col0);
    for (int jj = 0; jj < jmax; ++jj) {
        int col = col0 + jj;
        if (col <= row) continue;
        float4 bj = sbox[jj];
        float iw = fmaxf(fminf(bi.z, bj.z) - fmaxf(bi.x, bj.x), 0.f);
        float ih = fmaxf(fminf(bi.w, bj.w) - fmaxf(bi.y, bj.y), 0.f);
        float inter = iw * ih;
        float areaj = fmaxf(bj.z - bj.x, 0.f) * fmaxf(bj.w - bj.y, 0.f);
        float iou = inter / (areai + areaj - inter + 1e-8f);
        if (iou > 0.7f) bits |= (1ull << jj);
    }
    g_mask[(size_t)row * NWORDS + cb] = bits;
}

// ---------------- greedy NMS reduce ----------------
__global__ void __launch_bounds__(256) k_reduce() {
    __shared__ unsigned long long s_remv[NWORDS];
    __shared__ unsigned long long s_diag[64];
    __shared__ unsigned long long s_keepw;
    const int n = g_count;
    const int nb = (n + 63) >> 6;
    const int tid = threadIdx.x;
    for (int i = tid; i < NWORDS; i += 256) s_remv[i] = 0;
    __syncthreads();
    const int q   = tid & 3;
    const int off = tid >> 2;
    for (int w = 0; w < nb; ++w) {
        if (tid < 64) {
            int row = w * 64 + tid;
            s_diag[tid] = (row < n) ? g_mask[(size_t)row * NWORDS + w] : 0ULL;
        }
        __syncthreads();
        if (tid == 0) {
            unsigned long long cur = s_remv[w];
            int rem = n - w * 64;
            if (rem < 64) cur |= (~0ULL) << rem;
            unsigned long long keepw = 0;
#pragma unroll
            for (int b = 0; b < 64; ++b) {
                if (!((cur >> b) & 1ULL)) {
                    keepw |= 1ULL << b;
                    cur |= s_diag[b];
                }
            }
            s_remv[w] = cur;
            s_keepw = keepw;
        }
        __syncthreads();
        const unsigned long long kw = s_keepw;
        for (int w2 = w + 1 + off; w2 < nb; w2 += 64) {
            unsigned long long accv = 0;
#pragma unroll
            for (int bb = 0; bb < 16; ++bb) {
                int b = q * 16 + bb;
                if ((kw >> b) & 1ULL)
                    accv |= g_mask[(size_t)(w * 64 + b) * NWORDS + w2];
            }
            if (accv) atomicOr(&s_remv[w2], accv);
        }
        __syncthreads();
        if (tid < 64) {
            if ((kw >> tid) & 1ULL) {
                int r = (unsigned int)g_items[w * 64 + tid];
                g_keep[r] = 1;
            }
        }
        __syncthreads();
    }
}

// ---------------- final output ----------------
__global__ void __launch_bounds__(256) k_output(float* __restrict__ out) {
    int i = blockIdx.x * 256 + threadIdx.x;
    if (i >= NBOX) return;
    float k = g_keep[i] ? 1.0f : 0.0f;
    float4 b = *(const float4*)&g_boxes[i * 4];
    out[i * 5 + 0] = b.x * k;
    out[i * 5 + 1] = b.y * k;
    out[i * 5 + 2] = b.z * k;
    out[i * 5 + 3] = b.w * k;
    out[i * 5 + 4] = g_conf[i] * k;
}

// ---------------- launch ----------------
extern "C" void kernel_launch(void* const* d_in, const int* in_sizes, int n_in,
                              void* d_out, int out_size) {
    const float *feat = nullptr, *anch = nullptr, *w1 = nullptr,
                *b1 = nullptr, *w2 = nullptr, *b2 = nullptr;
    for (int i = 0; i < n_in; ++i) {
        switch (in_sizes[i]) {
            case 1310720: feat = (const float*)d_in[i]; break;
            case 18:      anch = (const float*)d_in[i]; break;
            case 2949120: w1   = (const float*)d_in[i]; break;
            case 256:     b1   = (const float*)d_in[i]; break;
            case 13824:   w2   = (const float*)d_in[i]; break;
            case 54:      b2   = (const float*)d_in[i]; break;
            default: break;
        }
    }
    float* out = (float*)d_out;

    k_init<<<64, 256>>>();                        // 0
    k_repack<<<W1ELEMS / 256, 256>>>(w1);         // 1
    k_dummy<<<1, 32>>>();                         // 2 (keeps ncu capture slot on conv1)
    k_conv1<<<dim3(4, 16, 9), 128>>>(feat);       // 3
    k_act<<<1024, 256>>>(b1);                     // 4
    k_conv2<<<144, 64>>>(w2, b2, anch);           // 5

    k_sort_local4k<<<4, 1024>>>();
    k_sort_global<<<8, 1024>>>(8192, 4096);
    k_sort_finish4k<<<4, 1024>>>(8192);
    k_sort_global<<<8, 1024>>>(16384, 8192);
    k_sort_global<<<8, 1024>>>(16384, 4096);
    k_sort_finish4k<<<4, 1024>>>(16384);

    k_mask<<<dim3(NWORDS, NWORDS), 64>>>();
    k_reduce<<<1, 256>>>();
    k_output<<<36, 256>>>(out);
}

// round 4
// speedup vs baseline: 2.7488x; 1.1002x over previous
#include <cuda_runtime.h>
#include <stdint.h>

#define NANCH 9
#define NPIX  1024
#define NBOX  9216          // NPIX * NANCH
#define NWORDS 144          // ceil(NBOX/64)
#define SORT_CAP 16384
#define W1ELEMS (9*1280*256)

// packed f32x2 FMA (full-rate fp32 path on sm_103a)
#define FMA2(acc, a, b) asm("fma.rn.f32x2 %0, %1, %2, %0;" : "+l"(acc) : "l"(a), "l"(b))

__device__ __forceinline__ unsigned long long dup2(float a) {
    unsigned long long r;
    asm("mov.b64 %0, {%1, %1};" : "=l"(r) : "r"(__float_as_uint(a)));
    return r;
}

// ---------------- device scratch ----------------
__device__ float g_w1t[W1ELEMS];                 // w1 repacked [tap][c][oc]
__device__ float g_hp[9][256 * NPIX];            // conv1 partial sums per tap
__device__ float g_h[256 * NPIX];                // activated hidden
__device__ float g_boxes[NBOX * 4];
__device__ float g_conf[NBOX];
__device__ unsigned long long g_items[SORT_CAP]; // (~conf_bits<<32)|idx
__device__ int g_count;
__device__ unsigned long long g_mask[(size_t)NBOX * NWORDS];
__device__ unsigned char g_keep[NBOX];

// ---------------- init ----------------
__global__ void k_init() {
    int i = blockIdx.x * 256 + threadIdx.x;
    if (i < SORT_CAP) g_items[i] = ~0ULL;
    if (i < NBOX)     g_keep[i] = 0;
    if (i == 0)       g_count = 0;
}

__global__ void k_dummy() {}

// ---------------- repack w1 (o,c,t) -> (t,c,o) ----------------
__global__ void k_repack(const float* __restrict__ w1) {
    int i = blockIdx.x * 256 + threadIdx.x;
    if (i >= W1ELEMS) return;
    int o  = i & 255;
    int c  = (i >> 8) % 1280;
    int tp = i / (1280 * 256);
    g_w1t[i] = w1[(o * 1280 + c) * 9 + tp];
}

// ---------------- conv1: per-tap 128oc x 128px GEMM tile, f32x2 ----------------
// grid (2, 8, 9), 256 threads, 8 oc x 8 px per thread, K-tile 16
__global__ void __launch_bounds__(256) k_conv1(const float* __restrict__ feat) {
    __shared__ float As[2][16][128];   // [buf][k][oc]
    __shared__ float Bs[2][16][128];   // [buf][k][px]

    const int ocBase = blockIdx.x * 128;
    const int p0     = blockIdx.y * 128;
    const int tp     = blockIdx.z;
    const int dy = tp / 3 - 1, dx = tp % 3 - 1;
    const int sh = dy * 32 + dx;

    const int tid = threadIdx.x;
    // A loader: 2 x float4 per thread
    const int arow = tid >> 5;          // 0..7
    const int acol = (tid & 31) * 4;
    // B loader: 8 scalars per thread, lanes sweep px (coalesced)
    const int bpx  = tid & 127;
    const int brow = tid >> 7;          // 0..1
    const int p    = p0 + bpx;
    const int yy   = (p >> 5) + dy;
    const int xx   = (p & 31) + dx;
    const bool bok = ((unsigned)yy < 32u) && ((unsigned)xx < 32u);
    const int bsrc = p + sh;

    const float* wp = g_w1t + (size_t)tp * (1280 * 256) + ocBase;

    // compute mapping: 16x16 thread grid
    const int ty = tid >> 4;   // oc group 0..15
    const int tx = tid & 15;   // px group 0..15

    unsigned long long acc[8][4];
#pragma unroll
    for (int i = 0; i < 8; i++)
#pragma unroll
        for (int j = 0; j < 4; j++) acc[i][j] = 0ull;

    float4 a_reg0, a_reg1;
    float  b_reg[8];

    // prefetch tile 0
    a_reg0 = *(const float4*)(wp + arow * 256 + acol);
    a_reg1 = *(const float4*)(wp + (arow + 8) * 256 + acol);
#pragma unroll
    for (int i = 0; i < 8; i++) {
        int c = brow + i * 2;
        b_reg[i] = bok ? feat[c * 1024 + bsrc] : 0.f;
    }

    int buf = 0;
    for (int c0 = 0; c0 < 1280; c0 += 16) {
        *(float4*)&As[buf][arow][acol]     = a_reg0;
        *(float4*)&As[buf][arow + 8][acol] = a_reg1;
#pragma unroll
        for (int i = 0; i < 8; i++) Bs[buf][brow + i * 2][bpx] = b_reg[i];
        __syncthreads();

        if (c0 + 16 < 1280) {
            const int cn = c0 + 16;
            a_reg0 = *(const float4*)(wp + (cn + arow) * 256 + acol);
            a_reg1 = *(const float4*)(wp + (cn + arow + 8) * 256 + acol);
#pragma unroll
            for (int i = 0; i < 8; i++) {
                int c = cn + brow + i * 2;
                b_reg[i] = bok ? feat[c * 1024 + bsrc] : 0.f;
            }
        }

#pragma unroll
        for (int kk = 0; kk < 16; ++kk) {
            float4 a0 = *(const float4*)&As[buf][kk][ty * 8];
            float4 a1 = *(const float4*)&As[buf][kk][ty * 8 + 4];
            ulonglong2 bq0 = *(const ulonglong2*)&Bs[buf][kk][tx * 8];
            ulonglong2 bq1 = *(const ulonglong2*)&Bs[buf][kk][tx * 8 + 4];
            unsigned long long d;
            d = dup2(a0.x); FMA2(acc[0][0], d, bq0.x); FMA2(acc[0][1], d, bq0.y); FMA2(acc[0][2], d, bq1.x); FMA2(acc[0][3], d, bq1.y);
            d = dup2(a0.y); FMA2(acc[1][0], d, bq0.x); FMA2(acc[1][1], d, bq0.y); FMA2(acc[1][2], d, bq1.x); FMA2(acc[1][3], d, bq1.y);
            d = dup2(a0.z); FMA2(acc[2][0], d, bq0.x); FMA2(acc[2][1], d, bq0.y); FMA2(acc[2][2], d, bq1.x); FMA2(acc[2][3], d, bq1.y);
            d = dup2(a0.w); FMA2(acc[3][0], d, bq0.x); FMA2(acc[3][1], d, bq0.y); FMA2(acc[3][2], d, bq1.x); FMA2(acc[3][3], d, bq1.y);
            d = dup2(a1.x); FMA2(acc[4][0], d, bq0.x); FMA2(acc[4][1], d, bq0.y); FMA2(acc[4][2], d, bq1.x); FMA2(acc[4][3], d, bq1.y);
            d = dup2(a1.y); FMA2(acc[5][0], d, bq0.x); FMA2(acc[5][1], d, bq0.y); FMA2(acc[5][2], d, bq1.x); FMA2(acc[5][3], d, bq1.y);
            d = dup2(a1.z); FMA2(acc[6][0], d, bq0.x); FMA2(acc[6][1], d, bq0.y); FMA2(acc[6][2], d, bq1.x); FMA2(acc[6][3], d, bq1.y);
            d = dup2(a1.w); FMA2(acc[7][0], d, bq0.x); FMA2(acc[7][1], d, bq0.y); FMA2(acc[7][2], d, bq1.x); FMA2(acc[7][3], d, bq1.y);
        }
        buf ^= 1;
    }

    // epilogue: 8 oc rows x 8 px
    const int oc = ocBase + ty * 8;
    const int px = p0 + tx * 8;
#pragma unroll
    for (int i = 0; i < 8; i++) {
        float* dst = g_hp[tp] + (size_t)(oc + i) * 1024 + px;
#pragma unroll
        for (int j = 0; j < 4; j++)
            *(unsigned long long*)(dst + 2 * j) = acc[i][j];
    }
}

// ---------------- combine 9 partials + bias + leaky relu ----------------
__global__ void __launch_bounds__(256) k_act(const float* __restrict__ b1) {
    int i = blockIdx.x * 256 + threadIdx.x;   // 262144 total
    float v = g_hp[0][i];
#pragma unroll
    for (int z = 1; z < 9; z++) v += g_hp[z][i];
    v += b1[i >> 10];
    v = (v > 0.f) ? v : 0.01f * v;
    g_h[i] = v;
}

// ---------------- conv2 (1x1) + sigmoid + decode + compaction ----------------
__global__ void __launch_bounds__(64) k_conv2(const float* __restrict__ w2,
                                              const float* __restrict__ b2,
                                              const float* __restrict__ anch) {
    __shared__ float sw[5][256];
    const int t = blockIdx.x * 64 + threadIdx.x;
    const int a = t >> 10;
    const int p = t & 1023;
    const int F[5] = {0, 2, 3, 4, 5};
#pragma unroll
    for (int f = 0; f < 5; ++f)
        for (int c = threadIdx.x; c < 256; c += 64)
            sw[f][c] = w2[(a * 6 + F[f]) * 256 + c];
    __syncthreads();
    float s0 = 0.f, s1 = 0.f, s2 = 0.f, s3 = 0.f, s4 = 0.f;
#pragma unroll 4
    for (int cc = 0; cc < 256; ++cc) {
        float hv = g_h[cc * 1024 + p];
        s0 = fmaf(sw[0][cc], hv, s0);
        s1 = fmaf(sw[1][cc], hv, s1);
        s2 = fmaf(sw[2][cc], hv, s2);
        s3 = fmaf(sw[3][cc], hv, s3);
        s4 = fmaf(sw[4][cc], hv, s4);
    }
    float logit = s0 + b2[a * 6 + 0];
    float tx = s1 + b2[a * 6 + 2];
    float ty = s2 + b2[a * 6 + 3];
    float tw = s3 + b2[a * 6 + 4];
    float th = s4 + b2[a * 6 + 5];
    float aw = anch[a * 2 + 0], ah = anch[a * 2 + 1];
    float cx = (float)(p & 31) + 0.5f;
    float cy = (float)(p >> 5) + 0.5f;
    float pcx = cx + tx * aw;
    float pcy = cy + ty * ah;
    float pw = aw * expf(tw);
    float ph = ah * expf(th);
    float conf = 1.0f / (1.0f + expf(-logit));
    int r = p * 9 + a;
    g_boxes[r * 4 + 0] = pcx - pw * 0.5f;
    g_boxes[r * 4 + 1] = pcy - ph * 0.5f;
    g_boxes[r * 4 + 2] = pcx + pw * 0.5f;
    g_boxes[r * 4 + 3] = pcy + ph * 0.5f;
    g_conf[r] = conf;
    if (conf > 0.5f) {
        int j = atomicAdd(&g_count, 1);
        unsigned int sb = __float_as_uint(conf);
        g_items[j] = ((unsigned long long)(~sb) << 32) | (unsigned int)r;
    }
}

// ---------------- bitonic sort (ascending), 4096-elem shared chunks ----------------
__global__ void __launch_bounds__(1024) k_sort_local4k() {
    __shared__ unsigned long long s[4096];
    const int base = blockIdx.x * 4096;
    const int tid = threadIdx.x;
#pragma unroll
    for (int e = 0; e < 4; e++) s[tid + e * 1024] = g_items[base + tid + e * 1024];
    __syncthreads();
    for (int k = 2; k <= 4096; k <<= 1) {
        for (int j = k >> 1; j > 0; j >>= 1) {
#pragma unroll
            for (int e = 0; e < 2; e++) {
                int t = tid + e * 1024;
                int i = ((t & ~(j - 1)) << 1) | (t & (j - 1));
                int l = i + j;
                bool up = (((base + i) & k) == 0);
                unsigned long long x = s[i], y = s[l];
                if (up ? (x > y) : (x < y)) { s[i] = y; s[l] = x; }
            }
            __syncthreads();
        }
    }
#pragma unroll
    for (int e = 0; e < 4; e++) g_items[base + tid + e * 1024] = s[tid + e * 1024];
}

__global__ void __launch_bounds__(1024) k_sort_global(int k, int j) {
    int t = blockIdx.x * 1024 + threadIdx.x;
    int i = ((t & ~(j - 1)) << 1) | (t & (j - 1));
    int l = i + j;
    bool up = ((i & k) == 0);
    unsigned long long x = g_items[i], y = g_items[l];
    if (up ? (x > y) : (x < y)) { g_items[i] = y; g_items[l] = x; }
}

__global__ void __launch_bounds__(1024) k_sort_finish4k(int k) {
    __shared__ unsigned long long s[4096];
    const int base = blockIdx.x * 4096;
    const int tid = threadIdx.x;
#pragma unroll
    for (int e = 0; e < 4; e++) s[tid + e * 1024] = g_items[base + tid + e * 1024];
    __syncthreads();
    for (int j = 2048; j > 0; j >>= 1) {
#pragma unroll
        for (int e = 0; e < 2; e++) {
            int t = tid + e * 1024;
            int i = ((t & ~(j - 1)) << 1) | (t & (j - 1));
            int l = i + j;
            bool up = (((base + i) & k) == 0);
            unsigned long long x = s[i], y = s[l];
            if (up ? (x > y) : (x < y)) { s[i] = y; s[l] = x; }
        }
        __syncthreads();
    }
#pragma unroll
    for (int e = 0; e < 4; e++) g_items[base + tid + e * 1024] = s[tid + e * 1024];
}

// ---------------- NMS bitmask build ----------------
__global__ void __launch_bounds__(64) k_mask() {
    const int n = g_count;
    const int rb = blockIdx.y, cb = blockIdx.x;
    if (cb < rb) return;
    if (rb * 64 >= n) return;
    if (cb * 64 >= n) return;
    __shared__ float4 sbox[64];
    const int tid = threadIdx.x;
    const int col0 = cb * 64;
    if (col0 + tid < n) {
        int r = (unsigned int)g_items[col0 + tid];
        sbox[tid] = *(const float4*)&g_boxes[r * 4];
    }
    __syncthreads();
    const int row = rb * 64 + tid;
    if (row >= n) return;
    int rr = (unsigned int)g_items[row];
    float4 bi = *(const float4*)&g_boxes[rr * 4];
    float areai = fmaxf(bi.z - bi.x, 0.f) * fmaxf(bi.w - bi.y, 0.f);
    unsigned long long bits = 0;
    int jmax = min(64, n - col0);
    for (int jj = 0; jj < jmax; ++jj) {
        int col = col0 + jj;
        if (col <= row) continue;
        float4 bj = sbox[jj];
        float iw = fmaxf(fminf(bi.z, bj.z) - fmaxf(bi.x, bj.x), 0.f);
        float ih = fmaxf(fminf(bi.w, bj.w) - fmaxf(bi.y, bj.y), 0.f);
        float inter = iw * ih;
        float areaj = fmaxf(bj.z - bj.x, 0.f) * fmaxf(bj.w - bj.y, 0.f);
        float iou = inter / (areai + areaj - inter + 1e-8f);
        if (iou > 0.7f) bits |= (1ull << jj);
    }
    g_mask[(size_t)row * NWORDS + cb] = bits;
}

// ---------------- greedy NMS reduce: ffs chain + diag prefetch ----------------
__global__ void __launch_bounds__(256) k_reduce() {
    __shared__ unsigned long long s_remv[NWORDS];
    __shared__ unsigned long long s_diag[2][64];
    __shared__ unsigned long long s_keepw;
    const int n = g_count;
    const int nb = (n + 63) >> 6;
    const int tid = threadIdx.x;
    for (int i = tid; i < NWORDS; i += 256) s_remv[i] = 0;
    if (tid < 64) s_diag[0][tid] = (tid < n) ? g_mask[(size_t)tid * NWORDS] : 0ULL;
    __syncthreads();
    const int q   = tid & 3;
    const int off = tid >> 2;
    for (int w = 0; w < nb; ++w) {
        const int pb = w & 1;
        // warps 2-3: prefetch next word's diagonal into the other buffer
        if (tid >= 64 && tid < 128) {
            int t2 = tid - 64;
            int w1 = w + 1;
            if (w1 < nb) {
                int row = w1 * 64 + t2;
                s_diag[pb ^ 1][t2] = (row < n) ? g_mask[(size_t)row * NWORDS + w1] : 0ULL;
            }
        }
        // thread 0: greedy chain over kept bits only
        if (tid == 0) {
            unsigned long long cur = s_remv[w];
            int rem = n - w * 64;
            if (rem < 64) cur |= (~0ULL) << rem;
            unsigned long long keepw = 0;
            unsigned long long alive = ~cur;
            while (alive) {
                int b = __ffsll((long long)alive) - 1;
                keepw |= 1ULL << b;
                cur |= s_diag[pb][b];
                alive = (~cur) & ~((2ULL << b) - 1ULL);
            }
            s_keepw = keepw;
        }
        __syncthreads();
        const unsigned long long kw = s_keepw;
        for (int w2 = w + 1 + off; w2 < nb; w2 += 64) {
            unsigned long long accv = 0;
#pragma unroll
            for (int bb = 0; bb < 16; ++bb) {
                int b = q * 16 + bb;
                if ((kw >> b) & 1ULL)
                    accv |= g_mask[(size_t)(w * 64 + b) * NWORDS + w2];
            }
            if (accv) atomicOr(&s_remv[w2], accv);
        }
        // warps 4-5: write keep flags concurrently with OR phase
        if (tid >= 128 && tid < 192) {
            int t2 = tid - 128;
            if ((kw >> t2) & 1ULL) {
                int r = (unsigned int)g_items[w * 64 + t2];
                g_keep[r] = 1;
            }
        }
        __syncthreads();
    }
}

// ---------------- final output ----------------
__global__ void __launch_bounds__(256) k_output(float* __restrict__ out) {
    int i = blockIdx.x * 256 + threadIdx.x;
    if (i >= NBOX) return;
    float k = g_keep[i] ? 1.0f : 0.0f;
    float4 b = *(const float4*)&g_boxes[i * 4];
    out[i * 5 + 0] = b.x * k;
    out[i * 5 + 1] = b.y * k;
    out[i * 5 + 2] = b.z * k;
    out[i * 5 + 3] = b.w * k;
    out[i * 5 + 4] = g_conf[i] * k;
}

// ---------------- launch ----------------
extern "C" void kernel_launch(void* const* d_in, const int* in_sizes, int n_in,
                              void* d_out, int out_size) {
    const float *feat = nullptr, *anch = nullptr, *w1 = nullptr,
                *b1 = nullptr, *w2 = nullptr, *b2 = nullptr;
    for (int i = 0; i < n_in; ++i) {
        switch (in_sizes[i]) {
            case 1310720: feat = (const float*)d_in[i]; break;
            case 18:      anch = (const float*)d_in[i]; break;
            case 2949120: w1   = (const float*)d_in[i]; break;
            case 256:     b1   = (const float*)d_in[i]; break;
            case 13824:   w2   = (const float*)d_in[i]; break;
            case 54:      b2   = (const float*)d_in[i]; break;
            default: break;
        }
    }
    float* out = (float*)d_out;

    k_init<<<64, 256>>>();                        // 0
    k_repack<<<W1ELEMS / 256, 256>>>(w1);         // 1
    k_dummy<<<1, 32>>>();                         // 2 (keeps ncu capture slot on conv1)
    k_conv1<<<dim3(2, 8, 9), 256>>>(feat);        // 3
    k_act<<<1024, 256>>>(b1);                     // 4
    k_conv2<<<144, 64>>>(w2, b2, anch);           // 5

    k_sort_local4k<<<4, 1024>>>();
    k_sort_global<<<8, 1024>>>(8192, 4096);
    k_sort_finish4k<<<4, 1024>>>(8192);
    k_sort_global<<<8, 1024>>>(16384, 8192);
    k_sort_global<<<8, 1024>>>(16384, 4096);
    k_sort_finish4k<<<4, 1024>>>(16384);

    k_mask<<<dim3(NWORDS, NWORDS), 64>>>();
    k_reduce<<<1, 256>>>();
    k_output<<<36, 256>>>(out);
}